// round 17
// baseline (speedup 1.0000x reference)
#include <cuda_runtime.h>
#include <cuda_fp16.h>
#include <cstdint>

// Problem constants
#define BDIM   16
#define DDIM   256
#define TDIM   4096
#define NTOK   (BDIM * TDIM)   // 65536
#define NEMB   1024
#define NBOOKS 8

#define NEG_INF (-3.0e38f)
#define DELTA   6.0e-3f        // ~11 sigma of single-term fp16 score error

// Padded fp16 codebook rows: 256 data + norm@256 + pad = 280 halves (560B, 35
// granules; 140 words % 32 = 12 -> 8-row LDSM spans disjoint banks, no swizzle)
#define ROWH   280
#define ROWB   560
#define NTBYTES (64 * ROWB)    // 35840 bytes per 64-emb stage chunk

// Scratch
__device__ float g_resid[NTOK * DDIM];                  // 64 MB residual (N, D)
__device__ float g_cn[NBOOKS * NEMB];                   // 0.5*||e||^2 (exact, for rescore)
__device__ __align__(16) __half g_bh[NBOOKS * NEMB * ROWH];   // padded fp16 books

// ---------------------------------------------------------------------------
// helpers
// ---------------------------------------------------------------------------
__device__ __forceinline__ uint32_t smem_u32(const void* p) {
    uint32_t a;
    asm("{ .reg .u64 t; cvta.to.shared.u64 t, %1; cvt.u32.u64 %0, t; }" : "=r"(a) : "l"(p));
    return a;
}

#define LDSM4(r, addr)                                                         \
    asm volatile("ldmatrix.sync.aligned.m8n8.x4.shared.b16 {%0,%1,%2,%3}, [%4];" \
        : "=r"((r)[0]), "=r"((r)[1]), "=r"((r)[2]), "=r"((r)[3]) : "r"(addr))

#define MMA_F16(d, a, b0, b1)                                                  \
    asm volatile("mma.sync.aligned.m16n8k16.row.col.f32.f16.f16.f32 "          \
        "{%0,%1,%2,%3}, {%4,%5,%6,%7}, {%8,%9}, {%0,%1,%2,%3};"                \
        : "+f"((d)[0]), "+f"((d)[1]), "+f"((d)[2]), "+f"((d)[3])               \
        : "r"((a)[0]), "r"((a)[1]), "r"((a)[2]), "r"((a)[3]), "r"(b0), "r"(b1))

// one-shot bulk copy gmem -> smem, completing on an mbarrier
#define BULK_G2S(dst, src, bytes, mbar)                                        \
    asm volatile("cp.async.bulk.shared::cluster.global.mbarrier::complete_tx::bytes " \
        "[%0], [%1], %2, [%3];"                                                \
        :: "r"(dst), "l"(src), "r"(bytes), "r"(mbar) : "memory")

#define MBAR_INIT(mb, c) asm volatile("mbarrier.init.shared.b64 [%0], %1;" :: "r"(mb), "r"(c) : "memory")
#define MBAR_EXPECT_TX(mb, tx) asm volatile("mbarrier.arrive.expect_tx.shared.b64 _, [%0], %1;" :: "r"(mb), "r"(tx) : "memory")

#define MBAR_WAIT(mb, par) do {                                                   \
    uint32_t _m = (mb), _p = (par), _d;                                           \
    asm volatile("{\n\t.reg .pred p;\n\t"                                         \
        "mbarrier.try_wait.parity.acquire.cta.shared::cta.b64 p, [%1], %2;\n\t"   \
        "selp.b32 %0, 1, 0, p;\n\t}" : "=r"(_d) : "r"(_m), "r"(_p) : "memory");   \
    if (!_d) {                                                                    \
        asm volatile("{\n\t.reg .pred P1;\n\tWL_%=:\n\t"                          \
            "mbarrier.try_wait.parity.acquire.cta.shared::cta.b64 P1, [%0], %1, 0x989680;\n\t" \
            "@P1 bra.uni WD_%=;\n\tbra.uni WL_%=;\n\tWD_%=:\n\t}"                 \
            :: "r"(_m), "r"(_p) : "memory");                                      \
    }                                                                             \
} while (0)

__device__ __forceinline__ uint32_t pack_h2(float a, float b) {
    __half2 h2 = __halves2half2(__float2half_rn(a), __float2half_rn(b));
    return *reinterpret_cast<uint32_t*>(&h2);
}

// merge another (v1,i1,v2,i2) top-2 tuple into ours
__device__ __forceinline__ void top2_merge4(float& v1, int& i1, float& v2, int& i2,
                                            float ov1, int oi1, float ov2, int oi2) {
    if (ov1 > v1) {
        if (v1 > ov2) { v2 = v1; i2 = i1; }
        else          { v2 = ov2; i2 = oi2; }
        v1 = ov1; i1 = oi1;
    } else if (ov1 > v2) {
        v2 = ov1; i2 = oi1;
    }
}

// ---------------------------------------------------------------------------
// transpose init / finish kernels (proven)
// ---------------------------------------------------------------------------
__global__ void init_resid(const float* __restrict__ z) {
    __shared__ float tile[32][33];
    const int b = blockIdx.z, d0 = blockIdx.y * 32, t0 = blockIdx.x * 32;
    const int tx = threadIdx.x, ty = threadIdx.y;
#pragma unroll
    for (int j = 0; j < 32; j += 8)
        tile[ty + j][tx] = z[(b * DDIM + d0 + ty + j) * TDIM + t0 + tx];
    __syncthreads();
#pragma unroll
    for (int j = 0; j < 32; j += 8)
        g_resid[(b * TDIM + t0 + ty + j) * DDIM + d0 + tx] = tile[tx][ty + j];
}

__global__ void write_out(const float* __restrict__ z, float* __restrict__ out) {
    __shared__ float tile[32][33];
    const int b = blockIdx.z, d0 = blockIdx.y * 32, t0 = blockIdx.x * 32;
    const int tx = threadIdx.x, ty = threadIdx.y;
#pragma unroll
    for (int j = 0; j < 32; j += 8)
        tile[ty + j][tx] = g_resid[(b * TDIM + t0 + ty + j) * DDIM + d0 + tx];
    __syncthreads();
#pragma unroll
    for (int j = 0; j < 32; j += 8) {
        int zi = (b * DDIM + d0 + ty + j) * TDIM + t0 + tx;
        out[zi] = z[zi] - tile[tx][ty + j];
    }
}

// half squared norms + padded fp16 pack with norm baked at k=256
__global__ void prep_books(const float* __restrict__ books) {
    const int row  = blockIdx.x * 8 + (threadIdx.x >> 5);   // 0..8191
    const int lane = threadIdx.x & 31;
    const float4* er4 = (const float4*)(books + (size_t)row * DDIM);
    float4 v0 = er4[lane * 2];
    float4 v1 = er4[lane * 2 + 1];
    float s = v0.x*v0.x + v0.y*v0.y + v0.z*v0.z + v0.w*v0.w
            + v1.x*v1.x + v1.y*v1.y + v1.z*v1.z + v1.w*v1.w;
#pragma unroll
    for (int off = 16; off; off >>= 1) s += __shfl_xor_sync(0xffffffffu, s, off);
    const float cn = 0.5f * s;
    if (lane == 0) g_cn[row] = cn;

    uint4 H;
    H.x = pack_h2(v0.x, v0.y);
    H.y = pack_h2(v0.z, v0.w);
    H.z = pack_h2(v1.x, v1.y);
    H.w = pack_h2(v1.z, v1.w);
    *(uint4*)(g_bh + (size_t)row * ROWH + lane * 8) = H;
    if (lane < 3) {   // pad granules 32..34; granule 32 carries -0.5*||e||^2
        uint4 P = make_uint4(0, 0, 0, 0);
        if (lane == 0) P.x = pack_h2(-cn, 0.f);
        *(uint4*)(g_bh + (size_t)row * ROWH + 256 + lane * 8) = P;
    }
}

// ---------------------------------------------------------------------------
// Fused all-books VQ: single-term fp16 mma.sync, norm baked into K (17 ks),
// top-2 + candidate rescue, per-CTA book loop (tokens independent across books).
// 2 CTAs/SM, 512 threads = 16 warps (4 token-rows x 4 embed-cols), 64 tok/CTA.
// ---------------------------------------------------------------------------
#define OFF_A    0                 // 64 rows x 560B = 35840
#define OFF_B    35840             // 2 bufs x 35840 -> end 107520
#define OFF_MB   107520            // 2 x u64 mbarriers (+pad to 32)
#define OFF_V    107552            // 64 tok x 4 wc x (v1,i1,v2,i2) = 4096
#define OFF_BI   111648            // 64 i
#define SMEM_TC  111904

#define NTHREADS 512
#define TOK_CTA  64

__global__ void __launch_bounds__(NTHREADS, 2) vq_all(const float* __restrict__ books,
                                                      const int* __restrict__ nbu) {
    extern __shared__ char smem[];
    const uint32_t sbase = smem_u32(smem);
    const int tid = threadIdx.x, lane = tid & 31, wid = tid >> 5;
    const int wr = wid & 3, wc = wid >> 2;           // 4 x 4 warp grid
    const int gid = lane >> 2, tg = lane & 3;
    const int tok0 = blockIdx.x * TOK_CTA;

    float4* sV = (float4*)(smem + OFF_V);            // (v1, i1(asint), v2, i2)
    int*   sBI = (int*)(smem + OFF_BI);

    int nbooks = *nbu;
    if (nbooks > NBOOKS) nbooks = NBOOKS;
    if (nbooks < 0) nbooks = 0;
    const int gTotal = nbooks * 16;
    if (gTotal == 0) return;

    if (tid == 0) {
        MBAR_INIT(sbase + OFF_MB, 1);
        MBAR_INIT(sbase + OFF_MB + 8, 1);
    }
    __syncthreads();

    // prologue: issue B copy for global stage 0
    if (tid == 0) {
        MBAR_EXPECT_TX(sbase + OFF_MB, (uint32_t)NTBYTES);
        BULK_G2S(sbase + OFF_B, (const void*)g_bh, (uint32_t)NTBYTES, sbase + OFF_MB);
    }

    // ldmatrix per-lane address components (no swizzle: 35-granule rows)
    const int kg = lane >> 4;
    const uint32_t aBase = sbase + OFF_A + (wr * 16 + (lane & 15)) * ROWB;
    const uint32_t bRow  = (wc * 16 + (lane & 15)) * ROWB;

    int g = 0;   // global stage counter (book*16 + nt)

    for (int book = 0; book < nbooks; book++) {
        // ---- stage A: residual 64 tok x 256 k -> fp16, + unit column ----
#pragma unroll
        for (int u = 0; u < 4; u++) {
            int idx = tid + u * NTHREADS;     // 2048 16B-units: 64 rows x 32
            int t = idx >> 5, gg = idx & 31;
            const float4* rr = (const float4*)(g_resid + (size_t)(tok0 + t) * DDIM);
            float4 a = rr[gg * 2], b = rr[gg * 2 + 1];
            uint4 H;
            H.x = pack_h2(a.x, a.y);
            H.y = pack_h2(a.z, a.w);
            H.z = pack_h2(b.x, b.y);
            H.w = pack_h2(b.z, b.w);
            *(uint4*)(smem + OFF_A + t * ROWB + gg * 16) = H;
        }
        if (tid < 192) {                      // granules 32..34: unit col + pad
            int t = tid / 3, p = tid - t * 3;
            uint4 P = make_uint4(0, 0, 0, 0);
            if (p == 0) P.x = pack_h2(1.f, 0.f);
            *(uint4*)(smem + OFF_A + t * ROWB + 512 + p * 16) = P;
        }

        // per-thread running top-2 for each of 2 token rows
        float tv1[2], tv2[2];
        int   ti1[2], ti2[2];
#pragma unroll
        for (int s = 0; s < 2; s++) {
            tv1[s] = NEG_INF; tv2[s] = NEG_INF;
            ti1[s] = 1 << 30; ti2[s] = 1 << 30;
        }

        // ---- 16-stage mainloop (64 embeds per stage, 17 ks incl. norm) ----
        for (int nt = 0; nt < 16; nt++, g++) {
            const int buf = g & 1;
            __syncthreads();     // prior stage reads done; A staged (nt==0)

            if (tid == 0 && g + 1 < gTotal) {
                const uint32_t mb1 = sbase + OFF_MB + (buf ^ 1) * 8;
                MBAR_EXPECT_TX(mb1, (uint32_t)NTBYTES);
                BULK_G2S(sbase + OFF_B + (buf ^ 1) * NTBYTES,
                         (const void*)(g_bh + (size_t)(g + 1) * 64 * ROWH),
                         (uint32_t)NTBYTES, mb1);
            }

            MBAR_WAIT(sbase + OFF_MB + buf * 8, (g >> 1) & 1);   // B(g) landed

            float acc[2][4];
#pragma unroll
            for (int h = 0; h < 2; h++)
#pragma unroll
                for (int q = 0; q < 4; q++) acc[h][q] = 0.f;

            const uint32_t Bb = sbase + OFF_B + buf * NTBYTES;

#pragma unroll
            for (int ks = 0; ks < 17; ks++) {
                const int goff = (ks * 2 + kg) * 16;
                uint32_t ah[4], bh[4];
                LDSM4(ah, aBase + goff);
                LDSM4(bh, Bb + bRow + goff);

                MMA_F16(acc[0], ah, bh[0], bh[2]);
                MMA_F16(acc[1], ah, bh[1], bh[3]);
            }

            // fold 8 raw scores/thread into running top-2 (norm already in acc)
#pragma unroll
            for (int rh = 0; rh < 2; rh++)
#pragma unroll
                for (int h = 0; h < 2; h++)
#pragma unroll
                    for (int c = 0; c < 2; c++) {
                        float s = acc[h][rh * 2 + c];
                        int  ii = nt * 64 + wc * 16 + h * 8 + tg * 2 + c;
                        if (s > tv1[rh]) {
                            tv2[rh] = tv1[rh]; ti2[rh] = ti1[rh];
                            tv1[rh] = s;       ti1[rh] = ii;
                        } else if (s > tv2[rh]) {
                            tv2[rh] = s; ti2[rh] = ii;
                        }
                    }
        }

        // merge top-2 across the 4 quad lanes (same token rows, different cols)
#pragma unroll
        for (int off = 1; off <= 2; off <<= 1)
#pragma unroll
            for (int s = 0; s < 2; s++) {
                float ov1 = __shfl_xor_sync(0xffffffffu, tv1[s], off);
                int   oi1 = __shfl_xor_sync(0xffffffffu, ti1[s], off);
                float ov2 = __shfl_xor_sync(0xffffffffu, tv2[s], off);
                int   oi2 = __shfl_xor_sync(0xffffffffu, ti2[s], off);
                top2_merge4(tv1[s], ti1[s], tv2[s], ti2[s], ov1, oi1, ov2, oi2);
            }
        __syncthreads();   // mainloop drained before sV timeline reuse
        if (tg == 0) {
#pragma unroll
            for (int s = 0; s < 2; s++) {
                int row = wr * 16 + s * 8 + gid;
                sV[row * 4 + wc] = make_float4(tv1[s], __int_as_float(ti1[s]),
                                               tv2[s], __int_as_float(ti2[s]));
            }
        }
        __syncthreads();

        // per-token final merge + (rare) exact candidate rescore
        const float* ebk = books + (size_t)book * NEMB * DDIM;
        const float* cnb = g_cn + book * NEMB;
        if (tid < TOK_CTA) {
            float4 e0 = sV[tid * 4];
            float V1 = e0.x; int I1 = __float_as_int(e0.y);
            float V2 = e0.z; int I2 = __float_as_int(e0.w);
            int cand[8];
            cand[0] = I1; cand[4] = I2;
#pragma unroll
            for (int w = 1; w < 4; w++) {
                float4 e = sV[tid * 4 + w];
                cand[w] = __float_as_int(e.y);
                cand[4 + w] = __float_as_int(e.w);
                top2_merge4(V1, I1, V2, I2,
                            e.x, __float_as_int(e.y), e.z, __float_as_int(e.w));
            }

            int bi = I1;
            if (V1 - V2 <= DELTA) {
                const float4* rr = (const float4*)(g_resid + (size_t)(tok0 + tid) * DDIM);
                float best = NEG_INF; int bidx = 1 << 30;
#pragma unroll
                for (int c = 0; c < 8; c++) {
                    const float4* er = (const float4*)(ebk + (size_t)cand[c] * DDIM);
                    float a = 0.f;
#pragma unroll 8
                    for (int k = 0; k < 64; k++) {
                        float4 x = rr[k], y = er[k];
                        a = fmaf(x.x, y.x, a); a = fmaf(x.y, y.y, a);
                        a = fmaf(x.z, y.z, a); a = fmaf(x.w, y.w, a);
                    }
                    float s = a - cnb[cand[c]];
                    if (s > best || (s == best && cand[c] < bidx)) { best = s; bidx = cand[c]; }
                }
                bi = bidx;
            }
            sBI[tid] = bi;
        }
        __syncthreads();

        // residual update in place (exact fp32 codebook rows; L2-resident)
#pragma unroll
        for (int u = 0; u < 8; u++) {
            int i = tid + u * NTHREADS;       // 4096 = 64 tok x 64 float4
            int t = i >> 6, d4 = i & 63;
            int idx = sBI[t];
            float4 q = ((const float4*)(ebk + (size_t)idx * DDIM))[d4];
            float4* rp = ((float4*)(g_resid + (size_t)(tok0 + t) * DDIM)) + d4;
            float4 r = *rp;
            r.x -= q.x; r.y -= q.y; r.z -= q.z; r.w -= q.w;
            *rp = r;
        }
        __syncthreads();   // update visible before next book's A staging
    }
}

// ---------------------------------------------------------------------------
extern "C" void kernel_launch(void* const* d_in, const int* in_sizes, int n_in,
                              void* d_out, int out_size) {
    const float* z     = (const float*)d_in[0];
    const float* books = (const float*)d_in[1];
    const int*   nbu   = (const int*)d_in[2];
    float*       out   = (float*)d_out;

    cudaFuncSetAttribute(vq_all, cudaFuncAttributeMaxDynamicSharedMemorySize, SMEM_TC);

    dim3 tgrid(TDIM / 32, DDIM / 32, BDIM);
    dim3 tblk(32, 8);

    init_resid<<<tgrid, tblk>>>(z);
    prep_books<<<(NBOOKS * NEMB) / 8, 256>>>(books);
    vq_all<<<NTOK / TOK_CTA, NTHREADS, SMEM_TC>>>(books, nbu);
    write_out<<<tgrid, tblk>>>(z, out);
}